// round 2
// baseline (speedup 1.0000x reference)
#include <cuda_runtime.h>
#include <cuda_bf16.h>
#include <cstdint>

// Problem shape (fixed for this dataset entry)
#define BATCH 16
#define SQ    2048
#define SK    2048
#define DK    128
#define DV    128

// ---------------------------------------------------------------------------
// Scratch (no allocations allowed -> __device__ globals)
// ---------------------------------------------------------------------------
static __device__ __align__(16) float g_scores[(size_t)BATCH * SQ * SK];      // 268 MB
static __device__ __align__(16) __nv_bfloat16 g_qhi[BATCH * SQ * DK];
static __device__ __align__(16) __nv_bfloat16 g_qlo[BATCH * SQ * DK];
static __device__ __align__(16) __nv_bfloat16 g_khi[BATCH * SK * DK];
static __device__ __align__(16) __nv_bfloat16 g_klo[BATCH * SK * DK];
static __device__ __align__(16) __nv_bfloat16 g_vthi[BATCH * DV * SK];        // V^T: [b][v][k]
static __device__ __align__(16) __nv_bfloat16 g_vtlo[BATCH * DV * SK];

// ---------------------------------------------------------------------------
// Helpers
// ---------------------------------------------------------------------------
__device__ __forceinline__ void split1(float x, __nv_bfloat16& h, __nv_bfloat16& l)
{
    h = __float2bfloat16_rn(x);
    l = __float2bfloat16_rn(x - __bfloat162float(h));
}

__device__ __forceinline__ unsigned pack_bf16(__nv_bfloat16 a, __nv_bfloat16 b)
{
    return (unsigned)__bfloat16_as_ushort(a) | ((unsigned)__bfloat16_as_ushort(b) << 16);
}

// mma.sync m16n8k16 row.col bf16 -> f32 accumulate
__device__ __forceinline__ void mma_bf16(float* c, const unsigned* a, unsigned b0, unsigned b1)
{
    asm volatile(
        "mma.sync.aligned.m16n8k16.row.col.f32.bf16.bf16.f32 "
        "{%0,%1,%2,%3}, {%4,%5,%6,%7}, {%8,%9}, {%0,%1,%2,%3};\n"
        : "+f"(c[0]), "+f"(c[1]), "+f"(c[2]), "+f"(c[3])
        : "r"(a[0]), "r"(a[1]), "r"(a[2]), "r"(a[3]), "r"(b0), "r"(b1));
}

// ---------------------------------------------------------------------------
// Prep 1: split Q or K (fp32 -> bf16 hi/lo), same [b][s][d] layout.
// which = 0 -> Q arrays, 1 -> K arrays. 1,048,576 threads, float4 each.
// ---------------------------------------------------------------------------
__global__ __launch_bounds__(256)
void qksplit_kernel(const float4* __restrict__ src, int which)
{
    int i = blockIdx.x * blockDim.x + threadIdx.x;   // 0 .. 1048575
    float4 f = src[i];
    __nv_bfloat16 h0, h1, h2, h3, l0, l1, l2, l3;
    split1(f.x, h0, l0); split1(f.y, h1, l1);
    split1(f.z, h2, l2); split1(f.w, h3, l3);
    unsigned* hi = (unsigned*)(which ? g_khi : g_qhi);
    unsigned* lo = (unsigned*)(which ? g_klo : g_qlo);
    hi[i * 2]     = pack_bf16(h0, h1);
    hi[i * 2 + 1] = pack_bf16(h2, h3);
    lo[i * 2]     = pack_bf16(l0, l1);
    lo[i * 2 + 1] = pack_bf16(l2, l3);
}

// ---------------------------------------------------------------------------
// Prep 2: transpose + split V: [b][k][v] fp32 -> Vt hi/lo [b][v][k] bf16.
// 32x32 smem tile transpose. grid (SK/32, DV/32, B), block (32, 8).
// ---------------------------------------------------------------------------
__global__ __launch_bounds__(256)
void vsplit_kernel(const float* __restrict__ V)
{
    __shared__ float t[32][33];
    const int k0 = blockIdx.x * 32, v0 = blockIdx.y * 32, b = blockIdx.z;
    const int x = threadIdx.x, y = threadIdx.y;
    const float* Vb = V + (size_t)b * SK * DV;
#pragma unroll
    for (int j = 0; j < 32; j += 8)
        t[y + j][x] = Vb[(size_t)(k0 + y + j) * DV + v0 + x];
    __syncthreads();
#pragma unroll
    for (int j = 0; j < 32; j += 8) {
        float val = t[x][y + j];                 // V[k0+x][v0+y+j]
        __nv_bfloat16 h, l; split1(val, h, l);
        size_t o = ((size_t)b * DV + v0 + y + j) * SK + k0 + x;
        g_vthi[o] = h;
        g_vtlo[o] = l;
    }
}

// ---------------------------------------------------------------------------
// Kernel A: S = (Q K^T) * 1/sqrt(DK) via 3-term bf16 MMA.
// CTA tile 128(q) x 128(k), 8 warps in 4x2, warp tile 32x64.
// Smem pitch 20 bf16/row (40B) -> conflict-spread LDS for fragments.
// ---------------------------------------------------------------------------
#define SPITCH 20

__global__ __launch_bounds__(256)
void qk_mma_kernel()
{
    const int kb = blockIdx.x, qb = blockIdx.y, b = blockIdx.z;

    __shared__ __nv_bfloat16 sAh[128 * SPITCH], sAl[128 * SPITCH];
    __shared__ __nv_bfloat16 sBh[128 * SPITCH], sBl[128 * SPITCH];

    const int tid  = threadIdx.x;
    const int wid  = tid >> 5, lane = tid & 31;
    const int g    = lane >> 2, tg = lane & 3;
    const int qoff = (wid >> 1) * 32;
    const int koff = (wid & 1) * 64;

    const size_t qbase = ((size_t)b * SQ + (size_t)qb * 128) * DK;
    const size_t kbase = ((size_t)b * SK + (size_t)kb * 128) * DK;

    float acc[2][8][4];
#pragma unroll
    for (int i = 0; i < 2; i++)
#pragma unroll
        for (int j = 0; j < 8; j++)
#pragma unroll
            for (int v = 0; v < 4; v++) acc[i][j][v] = 0.f;

    const int r  = tid >> 1;          // 0..127 (staging row)
    const int c8 = (tid & 1) * 8;     // 0 or 8

    for (int d0 = 0; d0 < DK; d0 += 16) {
        // ---- stage 128x16 bf16 tiles of Qhi/Qlo/Khi/Klo ----
        {
            size_t ga = qbase + (size_t)r * DK + d0 + c8;
            size_t gb = kbase + (size_t)r * DK + d0 + c8;
            uint4 ah = *(const uint4*)(g_qhi + ga);
            uint4 al = *(const uint4*)(g_qlo + ga);
            uint4 bh = *(const uint4*)(g_khi + gb);
            uint4 bl = *(const uint4*)(g_klo + gb);
            int s = r * SPITCH + c8;
            *(uint2*)(sAh + s)     = make_uint2(ah.x, ah.y);
            *(uint2*)(sAh + s + 4) = make_uint2(ah.z, ah.w);
            *(uint2*)(sAl + s)     = make_uint2(al.x, al.y);
            *(uint2*)(sAl + s + 4) = make_uint2(al.z, al.w);
            *(uint2*)(sBh + s)     = make_uint2(bh.x, bh.y);
            *(uint2*)(sBh + s + 4) = make_uint2(bh.z, bh.w);
            *(uint2*)(sBl + s)     = make_uint2(bl.x, bl.y);
            *(uint2*)(sBl + s + 4) = make_uint2(bl.z, bl.w);
        }
        __syncthreads();

        // ---- A fragments (hi & lo) for both m-tiles ----
        unsigned ah[2][4], al[2][4];
#pragma unroll
        for (int mt = 0; mt < 2; mt++) {
            int r0 = (qoff + mt * 16 + g) * SPITCH;
            int r8 = r0 + 8 * SPITCH;
            ah[mt][0] = *(const unsigned*)(sAh + r0 + 2 * tg);
            ah[mt][1] = *(const unsigned*)(sAh + r8 + 2 * tg);
            ah[mt][2] = *(const unsigned*)(sAh + r0 + 2 * tg + 8);
            ah[mt][3] = *(const unsigned*)(sAh + r8 + 2 * tg + 8);
            al[mt][0] = *(const unsigned*)(sAl + r0 + 2 * tg);
            al[mt][1] = *(const unsigned*)(sAl + r8 + 2 * tg);
            al[mt][2] = *(const unsigned*)(sAl + r0 + 2 * tg + 8);
            al[mt][3] = *(const unsigned*)(sAl + r8 + 2 * tg + 8);
        }

        // ---- B fragments + MMAs (hi*hi + hi*lo + lo*hi) ----
#pragma unroll
        for (int nt = 0; nt < 8; nt++) {
            int rn = (koff + nt * 8 + g) * SPITCH;
            unsigned bh0 = *(const unsigned*)(sBh + rn + 2 * tg);
            unsigned bh1 = *(const unsigned*)(sBh + rn + 2 * tg + 8);
            unsigned bl0 = *(const unsigned*)(sBl + rn + 2 * tg);
            unsigned bl1 = *(const unsigned*)(sBl + rn + 2 * tg + 8);
#pragma unroll
            for (int mt = 0; mt < 2; mt++) {
                mma_bf16(acc[mt][nt], ah[mt], bh0, bh1);
                mma_bf16(acc[mt][nt], ah[mt], bl0, bl1);
                mma_bf16(acc[mt][nt], al[mt], bh0, bh1);
            }
        }
        __syncthreads();
    }

    // ---- epilogue: scale + store S ----
    const float scale = 0.08838834764831845f;   // 1/sqrt(128)
    float* S = g_scores + ((size_t)b * SQ + (size_t)qb * 128) * SK + (size_t)kb * 128;
#pragma unroll
    for (int mt = 0; mt < 2; mt++)
#pragma unroll
        for (int nt = 0; nt < 8; nt++) {
            int qr = qoff + mt * 16 + g;
            int kc = koff + nt * 8 + 2 * tg;
            float2 v0 = make_float2(acc[mt][nt][0] * scale, acc[mt][nt][1] * scale);
            float2 v1 = make_float2(acc[mt][nt][2] * scale, acc[mt][nt][3] * scale);
            *(float2*)(S + (size_t)qr * SK + kc)       = v0;
            *(float2*)(S + (size_t)(qr + 8) * SK + kc) = v1;
        }
}

// ---------------------------------------------------------------------------
// Kernel B: row softmax with mask. One CTA (256 thr) per (b, q) row.
// Reads S from g_scores, writes P ONCE to pdst (= attn output when present,
// else back into g_scores). Max over all k pre-mask == reference semantics
// (shift-invariant).
// ---------------------------------------------------------------------------
__global__ __launch_bounds__(256)
void softmax_kernel(const int* __restrict__ mask, float* __restrict__ pdst)
{
    const int q = blockIdx.x;
    const int b = blockIdx.y;
    const size_t base = ((size_t)b * SQ + q) * SK;
    const float* row = g_scores + base;
    const int* mrow = mask + base;
    const int tid = threadIdx.x;

    float4 f0 = ((const float4*)row)[tid];
    float4 f1 = ((const float4*)row)[tid + 256];
    int4   m0 = ((const int4*)mrow)[tid];
    int4   m1 = ((const int4*)mrow)[tid + 256];

    float v[8] = {f0.x, f0.y, f0.z, f0.w, f1.x, f1.y, f1.z, f1.w};
    int   m[8] = {m0.x, m0.y, m0.z, m0.w, m1.x, m1.y, m1.z, m1.w};

    float mx = v[0];
#pragma unroll
    for (int i = 1; i < 8; i++) mx = fmaxf(mx, v[i]);

    __shared__ float red[8];
#pragma unroll
    for (int off = 16; off > 0; off >>= 1)
        mx = fmaxf(mx, __shfl_xor_sync(0xffffffffu, mx, off));
    if ((tid & 31) == 0) red[tid >> 5] = mx;
    __syncthreads();
    if (tid < 32) {
        float t = (tid < 8) ? red[tid] : -3.402823466e38f;
#pragma unroll
        for (int off = 4; off > 0; off >>= 1)
            t = fmaxf(t, __shfl_xor_sync(0xffffffffu, t, off));
        if (tid == 0) red[0] = t;
    }
    __syncthreads();
    mx = red[0];

    float e[8];
    float s = 0.f;
#pragma unroll
    for (int i = 0; i < 8; i++) {
        e[i] = (m[i] != 0) ? __expf(v[i] - mx) : 0.f;
        s += e[i];
    }
#pragma unroll
    for (int off = 16; off > 0; off >>= 1)
        s += __shfl_xor_sync(0xffffffffu, s, off);
    __shared__ float red2[8];
    if ((tid & 31) == 0) red2[tid >> 5] = s;
    __syncthreads();
    if (tid < 32) {
        float t = (tid < 8) ? red2[tid] : 0.f;
#pragma unroll
        for (int off = 4; off > 0; off >>= 1)
            t += __shfl_xor_sync(0xffffffffu, t, off);
        if (tid == 0) red2[0] = t;
    }
    __syncthreads();
    const float inv = 1.0f / red2[0];

    float4* prow = (float4*)(pdst + base);
    prow[tid]       = make_float4(e[0] * inv, e[1] * inv, e[2] * inv, e[3] * inv);
    prow[tid + 256] = make_float4(e[4] * inv, e[5] * inv, e[6] * inv, e[7] * inv);
}

// ---------------------------------------------------------------------------
// Kernel C: context = P @ V via 3-term bf16 MMA. P split on the fly during
// staging; V pre-split/transposed (g_vthi/g_vtlo, [b][v][k]).
// CTA tile 64(q) x 128(v), 8 warps in 2x4, warp tile 32x32.
// grid (SQ/64, B) = 512 CTAs.
// ---------------------------------------------------------------------------
__global__ __launch_bounds__(256)
void pv_mma_kernel(const float* __restrict__ P, float* __restrict__ ctx)
{
    const int qb = blockIdx.x, b = blockIdx.y;

    __shared__ __nv_bfloat16 sPh[64 * SPITCH], sPl[64 * SPITCH];
    __shared__ __nv_bfloat16 sVh[128 * SPITCH], sVl[128 * SPITCH];

    const int tid  = threadIdx.x;
    const int wid  = tid >> 5, lane = tid & 31;
    const int g    = lane >> 2, tg = lane & 3;
    const int qoff = (wid >> 2) * 32;
    const int noff = (wid & 3) * 32;

    const float* Pb = P + ((size_t)b * SQ + (size_t)qb * 64) * SK;
    const __nv_bfloat16* Vh = g_vthi + (size_t)b * DV * SK;
    const __nv_bfloat16* Vl = g_vtlo + (size_t)b * DV * SK;

    float acc[2][4][4];
#pragma unroll
    for (int i = 0; i < 2; i++)
#pragma unroll
        for (int j = 0; j < 4; j++)
#pragma unroll
            for (int v = 0; v < 4; v++) acc[i][j][v] = 0.f;

    const int rp = tid >> 2, cp = (tid & 3) * 4;   // P staging: 64 rows x 16
    const int rv = tid >> 1, cv = (tid & 1) * 8;   // V staging: 128 rows x 16

    for (int k0 = 0; k0 < SK; k0 += 16) {
        // ---- stage P (fp32 -> hi/lo bf16) ----
        {
            float4 f = *(const float4*)(Pb + (size_t)rp * SK + k0 + cp);
            __nv_bfloat16 h0, h1, h2, h3, l0, l1, l2, l3;
            split1(f.x, h0, l0); split1(f.y, h1, l1);
            split1(f.z, h2, l2); split1(f.w, h3, l3);
            int s = rp * SPITCH + cp;
            *(uint2*)(sPh + s) = make_uint2(pack_bf16(h0, h1), pack_bf16(h2, h3));
            *(uint2*)(sPl + s) = make_uint2(pack_bf16(l0, l1), pack_bf16(l2, l3));
        }
        // ---- stage V^T hi/lo ----
        {
            size_t gv = (size_t)rv * SK + k0 + cv;
            uint4 vh = *(const uint4*)(Vh + gv);
            uint4 vl = *(const uint4*)(Vl + gv);
            int s = rv * SPITCH + cv;
            *(uint2*)(sVh + s)     = make_uint2(vh.x, vh.y);
            *(uint2*)(sVh + s + 4) = make_uint2(vh.z, vh.w);
            *(uint2*)(sVl + s)     = make_uint2(vl.x, vl.y);
            *(uint2*)(sVl + s + 4) = make_uint2(vl.z, vl.w);
        }
        __syncthreads();

        unsigned ah[2][4], al[2][4];
#pragma unroll
        for (int mt = 0; mt < 2; mt++) {
            int r0 = (qoff + mt * 16 + g) * SPITCH;
            int r8 = r0 + 8 * SPITCH;
            ah[mt][0] = *(const unsigned*)(sPh + r0 + 2 * tg);
            ah[mt][1] = *(const unsigned*)(sPh + r8 + 2 * tg);
            ah[mt][2] = *(const unsigned*)(sPh + r0 + 2 * tg + 8);
            ah[mt][3] = *(const unsigned*)(sPh + r8 + 2 * tg + 8);
            al[mt][0] = *(const unsigned*)(sPl + r0 + 2 * tg);
            al[mt][1] = *(const unsigned*)(sPl + r8 + 2 * tg);
            al[mt][2] = *(const unsigned*)(sPl + r0 + 2 * tg + 8);
            al[mt][3] = *(const unsigned*)(sPl + r8 + 2 * tg + 8);
        }

#pragma unroll
        for (int nt = 0; nt < 4; nt++) {
            int rn = (noff + nt * 8 + g) * SPITCH;
            unsigned bh0 = *(const unsigned*)(sVh + rn + 2 * tg);
            unsigned bh1 = *(const unsigned*)(sVh + rn + 2 * tg + 8);
            unsigned bl0 = *(const unsigned*)(sVl + rn + 2 * tg);
            unsigned bl1 = *(const unsigned*)(sVl + rn + 2 * tg + 8);
#pragma unroll
            for (int mt = 0; mt < 2; mt++) {
                mma_bf16(acc[mt][nt], ah[mt], bh0, bh1);
                mma_bf16(acc[mt][nt], ah[mt], bl0, bl1);
                mma_bf16(acc[mt][nt], al[mt], bh0, bh1);
            }
        }
        __syncthreads();
    }

    // ---- epilogue: store context ----
    float* Cb = ctx + ((size_t)b * SQ + (size_t)qb * 64) * DV;
#pragma unroll
    for (int mt = 0; mt < 2; mt++)
#pragma unroll
        for (int nt = 0; nt < 4; nt++) {
            int qr = qoff + mt * 16 + g;
            int vc = noff + nt * 8 + 2 * tg;
            *(float2*)(Cb + (size_t)qr * DV + vc) =
                make_float2(acc[mt][nt][0], acc[mt][nt][1]);
            *(float2*)(Cb + (size_t)(qr + 8) * DV + vc) =
                make_float2(acc[mt][nt][2], acc[mt][nt][3]);
        }
}

// ---------------------------------------------------------------------------
// Launch
// ---------------------------------------------------------------------------
extern "C" void kernel_launch(void* const* d_in, const int* in_sizes, int n_in,
                              void* d_out, int out_size)
{
    const float* Q    = (const float*)d_in[0];
    const float* K    = (const float*)d_in[1];
    const float* V    = (const float*)d_in[2];
    const int*   mask = (const int*)d_in[3];
    float* out = (float*)d_out;

    const size_t CTX  = (size_t)BATCH * SQ * DV;   //  4,194,304
    const size_t ATTN = (size_t)BATCH * SQ * SK;   // 67,108,864

    float* ctx_out  = nullptr;
    float* attn_out = nullptr;
    const size_t osz = (size_t)out_size;
    if (osz == CTX + ATTN)      { ctx_out = out; attn_out = out + CTX; }
    else if (osz == ATTN)       { attn_out = out; }
    else if (osz == CTX)        { ctx_out = out; }
    else                        { ctx_out = out; if (osz >= CTX + ATTN) attn_out = out + CTX; }

    // Prep: split Q, K; transpose+split V
    qksplit_kernel<<<4096, 256>>>((const float4*)Q, 0);
    qksplit_kernel<<<4096, 256>>>((const float4*)K, 1);
    {
        dim3 grid(SK / 32, DV / 32, BATCH);
        vsplit_kernel<<<grid, dim3(32, 8)>>>(V);
    }

    // A: scores = Q K^T / sqrt(dk)
    {
        dim3 grid(SK / 128, SQ / 128, BATCH);
        qk_mma_kernel<<<grid, 256>>>();
    }

    // B: softmax -> P written once (to attn output when present)
    float* pdst = nullptr;
    // Need an address for the scratch fallback: take it via a kernel-visible
    // pointer. g_scores address is only valid in device code, so pass a tag:
    // use attn_out when available, else write back into g_scores (pdst = null
    // sentinel handled by passing g_scores through a device-side branch is
    // not possible for a pointer arg; instead, resolve here: when attn_out is
    // null we simply pass a null and the kernels use g_scores internally).
    pdst = attn_out;
    {
        dim3 grid(SQ, BATCH);
        if (pdst != nullptr)
            softmax_kernel<<<grid, 256>>>(mask, pdst);
        else {
            // fallback: in-place into g_scores via a device-side resolved ptr
            // (softmax_inplace variant below)
            extern __global__ void softmax_inplace_kernel(const int*);
            softmax_inplace_kernel<<<grid, 256>>>(mask);
        }
    }

    // C: context = P V
    if (ctx_out != nullptr) {
        dim3 grid(SQ / 64, BATCH);
        if (pdst != nullptr)
            pv_mma_kernel<<<grid, 256>>>(pdst, ctx_out);
        else {
            extern __global__ void pv_mma_scratch_kernel(float*);
            pv_mma_scratch_kernel<<<grid, 256>>>(ctx_out);
        }
    }
}

// ---------------------------------------------------------------------------
// Fallback variants that resolve g_scores on the device side (used only when
// the output layout lacks the attn region; expected path never uses these).
// ---------------------------------------------------------------------------
__global__ __launch_bounds__(256)
void softmax_inplace_kernel(const int* __restrict__ mask)
{
    // delegate: identical body with pdst = g_scores
    const int q = blockIdx.x;
    const int b = blockIdx.y;
    const size_t base = ((size_t)b * SQ + q) * SK;
    const float* row = g_scores + base;
    const int* mrow = mask + base;
    const int tid = threadIdx.x;

    float4 f0 = ((const float4*)row)[tid];
    float4 f1 = ((const float4*)row)[tid + 256];
    int4   m0 = ((const int4*)mrow)[tid];
    int4   m1 = ((const int4*)mrow)[tid + 256];

    float v[8] = {f0.x, f0.y, f0.z, f0.w, f1.x, f1.y, f1.z, f1.w};
    int   m[8] = {m0.x, m0.y, m0.z, m0.w, m1.x, m1.y, m1.z, m1.w};

    float mx = v[0];
#pragma unroll
    for (int i = 1; i < 8; i++) mx = fmaxf(mx, v[i]);

    __shared__ float red[8];
#pragma unroll
    for (int off = 16; off > 0; off >>= 1)
        mx = fmaxf(mx, __shfl_xor_sync(0xffffffffu, mx, off));
    if ((tid & 31) == 0) red[tid >> 5] = mx;
    __syncthreads();
    if (tid < 32) {
        float t = (tid < 8) ? red[tid] : -3.402823466e38f;
#pragma unroll
        for (int off = 4; off > 0; off >>= 1)
            t = fmaxf(t, __shfl_xor_sync(0xffffffffu, t, off));
        if (tid == 0) red[0] = t;
    }
    __syncthreads();
    mx = red[0];

    float e[8];
    float s = 0.f;
#pragma unroll
    for (int i = 0; i < 8; i++) {
        e[i] = (m[i] != 0) ? __expf(v[i] - mx) : 0.f;
        s += e[i];
    }
#pragma unroll
    for (int off = 16; off > 0; off >>= 1)
        s += __shfl_xor_sync(0xffffffffu, s, off);
    __shared__ float red2[8];
    if ((tid & 31) == 0) red2[tid >> 5] = s;
    __syncthreads();
    if (tid < 32) {
        float t = (tid < 8) ? red2[tid] : 0.f;
#pragma unroll
        for (int off = 4; off > 0; off >>= 1)
            t += __shfl_xor_sync(0xffffffffu, t, off);
        if (tid == 0) red2[0] = t;
    }
    __syncthreads();
    const float inv = 1.0f / red2[0];

    float4* prow = (float4*)(g_scores + base);
    prow[tid]       = make_float4(e[0] * inv, e[1] * inv, e[2] * inv, e[3] * inv);
    prow[tid + 256] = make_float4(e[4] * inv, e[5] * inv, e[6] * inv, e[7] * inv);
}

__global__ __launch_bounds__(256)
void pv_mma_scratch_kernel(float* __restrict__ ctx)
{
    // Thin wrapper: identical to pv_mma_kernel but P = g_scores.
    const int qb = blockIdx.x, b = blockIdx.y;

    __shared__ __nv_bfloat16 sPh[64 * SPITCH], sPl[64 * SPITCH];
    __shared__ __nv_bfloat16 sVh[128 * SPITCH], sVl[128 * SPITCH];

    const int tid  = threadIdx.x;
    const int wid  = tid >> 5, lane = tid & 31;
    const int g    = lane >> 2, tg = lane & 3;
    const int qoff = (wid >> 2) * 32;
    const int noff = (wid & 3) * 32;

    const float* Pb = g_scores + ((size_t)b * SQ + (size_t)qb * 64) * SK;
    const __nv_bfloat16* Vh = g_vthi + (size_t)b * DV * SK;
    const __nv_bfloat16* Vl = g_vtlo + (size_t)b * DV * SK;

    float acc[2][4][4];
#pragma unroll
    for (int i = 0; i < 2; i++)
#pragma unroll
        for (int j = 0; j < 4; j++)
#pragma unroll
            for (int v = 0; v < 4; v++) acc[i][j][v] = 0.f;

    const int rp = tid >> 2, cp = (tid & 3) * 4;
    const int rv = tid >> 1, cv = (tid & 1) * 8;

    for (int k0 = 0; k0 < SK; k0 += 16) {
        {
            float4 f = *(const float4*)(Pb + (size_t)rp * SK + k0 + cp);
            __nv_bfloat16 h0, h1, h2, h3, l0, l1, l2, l3;
            split1(f.x, h0, l0); split1(f.y, h1, l1);
            split1(f.z, h2, l2); split1(f.w, h3, l3);
            int s = rp * SPITCH + cp;
            *(uint2*)(sPh + s) = make_uint2(pack_bf16(h0, h1), pack_bf16(h2, h3));
            *(uint2*)(sPl + s) = make_uint2(pack_bf16(l0, l1), pack_bf16(l2, l3));
        }
        {
            size_t gv = (size_t)rv * SK + k0 + cv;
            uint4 vh = *(const uint4*)(Vh + gv);
            uint4 vl = *(const uint4*)(Vl + gv);
            int s = rv * SPITCH + cv;
            *(uint2*)(sVh + s)     = make_uint2(vh.x, vh.y);
            *(uint2*)(sVh + s + 4) = make_uint2(vh.z, vh.w);
            *(uint2*)(sVl + s)     = make_uint2(vl.x, vl.y);
            *(uint2*)(sVl + s + 4) = make_uint2(vl.z, vl.w);
        }
        __syncthreads();

        unsigned ah[2][4], al[2][4];
#pragma unroll
        for (int mt = 0; mt < 2; mt++) {
            int r0 = (qoff + mt * 16 + g) * SPITCH;
            int r8 = r0 + 8 * SPITCH;
            ah[mt][0] = *(const unsigned*)(sPh + r0 + 2 * tg);
            ah[mt][1] = *(const unsigned*)(sPh + r8 + 2 * tg);
            ah[mt][2] = *(const unsigned*)(sPh + r0 + 2 * tg + 8);
            ah[mt][3] = *(const unsigned*)(sPh + r8 + 2 * tg + 8);
            al[mt][0] = *(const unsigned*)(sPl + r0 + 2 * tg);
            al[mt][1] = *(const unsigned*)(sPl + r8 + 2 * tg);
            al[mt][2] = *(const unsigned*)(sPl + r0 + 2 * tg + 8);
            al[mt][3] = *(const unsigned*)(sPl + r8 + 2 * tg + 8);
        }

#pragma unroll
        for (int nt = 0; nt < 4; nt++) {
            int rn = (noff + nt * 8 + g) * SPITCH;
            unsigned bh0 = *(const unsigned*)(sVh + rn + 2 * tg);
            unsigned bh1 = *(const unsigned*)(sVh + rn + 2 * tg + 8);
            unsigned bl0 = *(const unsigned*)(sVl + rn + 2 * tg);
            unsigned bl1 = *(const unsigned*)(sVl + rn + 2 * tg + 8);
#pragma unroll
            for (int mt = 0; mt < 2; mt++) {
                mma_bf16(acc[mt][nt], ah[mt], bh0, bh1);
                mma_bf16(acc[mt][nt], ah[mt], bl0, bl1);
                mma_bf16(acc[mt][nt], al[mt], bh0, bh1);
            }
        }
        __syncthreads();
    }

    float* Cb = ctx + ((size_t)b * SQ + (size_t)qb * 64) * DV;
#pragma unroll
    for (int mt = 0; mt < 2; mt++)
#pragma unroll
        for (int nt = 0; nt < 4; nt++) {
            int qr = qoff + mt * 16 + g;
            int vc = noff + nt * 8 + 2 * tg;
            *(float2*)(Cb + (size_t)qr * DV + vc) =
                make_float2(acc[mt][nt][0], acc[mt][nt][1]);
            *(float2*)(Cb + (size_t)(qr + 8) * DV + vc) =
                make_float2(acc[mt][nt][2], acc[mt][nt][3]);
        }
}

// round 6
// speedup vs baseline: 1.3442x; 1.3442x over previous
#include <cuda_runtime.h>
#include <cuda_bf16.h>
#include <cstdint>

// Problem shape (fixed)
#define BATCH 16
#define SQ    2048
#define SK    2048
#define DK    128
#define DV    128

// ---------------------------------------------------------------------------
// Scratch (__device__ globals; no allocations allowed)
// Packed operand layout: per row, per 16-k chunk, 4 groups (tg=0..3) of 16B:
//   group t = { hi(2t,2t+1) , hi(2t+8,2t+9) , lo(2t,2t+1) , lo(2t+8,2t+9) }
// so ONE LDS.128 feeds a (hi+lo) half-fragment of m16n8k16.
// ---------------------------------------------------------------------------
static __device__ __align__(16) float g_scores[(size_t)BATCH * SQ * SK];        // 268 MB
static __device__ __align__(16) uint4 g_qpk[(size_t)BATCH * SQ * 32];           // 16.8 MB
static __device__ __align__(16) uint4 g_kpk[(size_t)BATCH * SK * 32];           // 16.8 MB
static __device__ __align__(16) uint4 g_vpk[(size_t)BATCH * DV * (SK / 16) * 4];// 16.8 MB (V^T)

// ---------------------------------------------------------------------------
// Helpers
// ---------------------------------------------------------------------------
__device__ __forceinline__ void split1(float x, __nv_bfloat16& h, __nv_bfloat16& l)
{
    h = __float2bfloat16_rn(x);
    l = __float2bfloat16_rn(x - __bfloat162float(h));
}

__device__ __forceinline__ unsigned pack_bf16(__nv_bfloat16 a, __nv_bfloat16 b)
{
    return (unsigned)__bfloat16_as_ushort(a) | ((unsigned)__bfloat16_as_ushort(b) << 16);
}

__device__ __forceinline__ void mma_bf16(float* c, const unsigned* a, unsigned b0, unsigned b1)
{
    asm volatile(
        "mma.sync.aligned.m16n8k16.row.col.f32.bf16.bf16.f32 "
        "{%0,%1,%2,%3}, {%4,%5,%6,%7}, {%8,%9}, {%0,%1,%2,%3};\n"
        : "+f"(c[0]), "+f"(c[1]), "+f"(c[2]), "+f"(c[3])
        : "r"(a[0]), "r"(a[1]), "r"(a[2]), "r"(a[3]), "r"(b0), "r"(b1));
}

__device__ __forceinline__ uint4 lds128(uint32_t addr)
{
    uint4 v;
    asm volatile("ld.shared.v4.u32 {%0,%1,%2,%3}, [%4];"
                 : "=r"(v.x), "=r"(v.y), "=r"(v.z), "=r"(v.w) : "r"(addr));
    return v;
}

__device__ __forceinline__ void sts128(uint32_t addr, uint4 v)
{
    asm volatile("st.shared.v4.u32 [%0], {%1,%2,%3,%4};"
                 :: "r"(addr), "r"(v.x), "r"(v.y), "r"(v.z), "r"(v.w) : "memory");
}

#define CP_ASYNC16(dst, src) \
    asm volatile("cp.async.cg.shared.global [%0], [%1], 16;\n" :: "r"(dst), "l"(src) : "memory")
#define CP_COMMIT() asm volatile("cp.async.commit_group;\n" ::: "memory")
#define CP_WAIT0()  asm volatile("cp.async.wait_group 0;\n" ::: "memory")

// Row stride in smem operand buffers: 2 chunks x 64B data + 64B pad = 192B.
// 192B = 48 words -> row bank base alternates by 16: conflict-free LDS.128 phases.
#define RSTRIDE 192

// ---------------------------------------------------------------------------
// Prep 1: pack Q or K fp32 -> interleaved hi/lo bf16 groups (device-side
// destination select; no host symbol queries, no static guards).
// unit = row*8 + chunk. 256 thr/block, BATCH*SQ*8/256 = 1024 blocks.
// ---------------------------------------------------------------------------
__global__ __launch_bounds__(256)
void qkprep_kernel(const float4* __restrict__ src, int which)
{
    const size_t unit = (size_t)blockIdx.x * 256 + threadIdx.x;   // row*8 + c
    const float4* s = src + unit * 4;
    float4 f0 = s[0], f1 = s[1], f2 = s[2], f3 = s[3];
    float f[16] = {f0.x, f0.y, f0.z, f0.w, f1.x, f1.y, f1.z, f1.w,
                   f2.x, f2.y, f2.z, f2.w, f3.x, f3.y, f3.z, f3.w};
    unsigned hw[8], lw[8];
#pragma unroll
    for (int i = 0; i < 8; i++) {
        __nv_bfloat16 ha, la, hb, lb;
        split1(f[2 * i], ha, la);
        split1(f[2 * i + 1], hb, lb);
        hw[i] = pack_bf16(ha, hb);
        lw[i] = pack_bf16(la, lb);
    }
    uint4* d = (which ? g_kpk : g_qpk) + unit * 4;
#pragma unroll
    for (int t = 0; t < 4; t++)
        d[t] = make_uint4(hw[t], hw[4 + t], lw[t], lw[4 + t]);
}

// ---------------------------------------------------------------------------
// Prep 2: transpose + split + pack V: [b][k][v] fp32 -> g_vpk [b][v][kchunk].
// Tile: 32 k x 64 v. block (64,4). grid (SK/32, DV/64, B).
// ---------------------------------------------------------------------------
__global__ __launch_bounds__(256)
void vprep_kernel(const float* __restrict__ V)
{
    __shared__ float tb[32][65];
    const int k0 = blockIdx.x * 32, v0 = blockIdx.y * 64, b = blockIdx.z;
    const int x = threadIdx.x, y = threadIdx.y;
    const float* Vb = V + (size_t)b * SK * DV;
#pragma unroll
    for (int j = 0; j < 32; j += 4)
        tb[j + y][x] = Vb[(size_t)(k0 + j + y) * DV + v0 + x];
    __syncthreads();

    const int tid = y * 64 + x;
    if (tid < 128) {
        const int vr = tid >> 1, c = tid & 1;
        float f[16];
#pragma unroll
        for (int i = 0; i < 16; i++) f[i] = tb[c * 16 + i][vr];
        unsigned hw[8], lw[8];
#pragma unroll
        for (int i = 0; i < 8; i++) {
            __nv_bfloat16 ha, la, hb, lb;
            split1(f[2 * i], ha, la);
            split1(f[2 * i + 1], hb, lb);
            hw[i] = pack_bf16(ha, hb);
            lw[i] = pack_bf16(la, lb);
        }
        uint4* d = g_vpk + (((size_t)b * DV + v0 + vr) * (SK / 16) + (k0 >> 4) + c) * 4;
#pragma unroll
        for (int t = 0; t < 4; t++)
            d[t] = make_uint4(hw[t], hw[4 + t], lw[t], lw[4 + t]);
    }
}

// ---------------------------------------------------------------------------
// Kernel A: S = (Q K^T)/sqrt(DK). CTA 128q x 128k, 8 warps (4x2), warp 32x64.
// k32 chunks, cp.async double buffer. Dynamic smem: 96 KB.
// ---------------------------------------------------------------------------
__global__ __launch_bounds__(256, 2)
void qk_mma_kernel()
{
    extern __shared__ char smem[];
    const int kb = blockIdx.x, qb = blockIdx.y, b = blockIdx.z;
    const int tid = threadIdx.x, wid = tid >> 5, lane = tid & 31;
    const int g = lane >> 2, tg = lane & 3;
    const int qoff = (wid >> 1) * 32, koff = (wid & 1) * 64;

    const uint4* qpk = g_qpk + ((size_t)b * SQ + (size_t)qb * 128) * 32;
    const uint4* kpk = g_kpk + ((size_t)b * SK + (size_t)kb * 128) * 32;

    const uint32_t sb = (uint32_t)__cvta_generic_to_shared(smem);
    const uint32_t sA[2] = { sb,          sb + 24576 };
    const uint32_t sB[2] = { sb + 49152,  sb + 73728 };

    // stage chunk-pair 0 (k = 0..31)
    {
#pragma unroll
        for (int i = 0; i < 4; i++) {
            int u = i * 256 + tid;
            int row = u >> 3, c = (u >> 2) & 1, t = u & 3;
            uint32_t doff = row * RSTRIDE + c * 64 + t * 16;
            CP_ASYNC16(sA[0] + doff, qpk + (size_t)row * 32 + c * 4 + t);
            CP_ASYNC16(sB[0] + doff, kpk + (size_t)row * 32 + c * 4 + t);
        }
        CP_COMMIT();
    }

    float acc[2][8][4];
#pragma unroll
    for (int i = 0; i < 2; i++)
#pragma unroll
        for (int j = 0; j < 8; j++)
#pragma unroll
            for (int v = 0; v < 4; v++) acc[i][j][v] = 0.f;

    for (int it = 0; it < 4; it++) {
        CP_WAIT0();
        __syncthreads();
        if (it < 3) {
            const int cg = (it + 1) * 2;
#pragma unroll
            for (int i = 0; i < 4; i++) {
                int u = i * 256 + tid;
                int row = u >> 3, c = (u >> 2) & 1, t = u & 3;
                uint32_t doff = row * RSTRIDE + c * 64 + t * 16;
                CP_ASYNC16(sA[(it + 1) & 1] + doff, qpk + (size_t)row * 32 + (cg + c) * 4 + t);
                CP_ASYNC16(sB[(it + 1) & 1] + doff, kpk + (size_t)row * 32 + (cg + c) * 4 + t);
            }
            CP_COMMIT();
        }
        const uint32_t a = sA[it & 1], bbuf = sB[it & 1];
#pragma unroll
        for (int c = 0; c < 2; c++) {
            uint4 av[2][2];
#pragma unroll
            for (int mt = 0; mt < 2; mt++) {
                int R = qoff + mt * 16 + g;
                av[mt][0] = lds128(a + R * RSTRIDE + c * 64 + tg * 16);
                av[mt][1] = lds128(a + (R + 8) * RSTRIDE + c * 64 + tg * 16);
            }
#pragma unroll
            for (int nt = 0; nt < 8; nt++) {
                uint4 bv = lds128(bbuf + (koff + nt * 8 + g) * RSTRIDE + c * 64 + tg * 16);
#pragma unroll
                for (int mt = 0; mt < 2; mt++) {
                    unsigned ah[4] = {av[mt][0].x, av[mt][1].x, av[mt][0].y, av[mt][1].y};
                    unsigned al[4] = {av[mt][0].z, av[mt][1].z, av[mt][0].w, av[mt][1].w};
                    mma_bf16(acc[mt][nt], ah, bv.x, bv.y);
                    mma_bf16(acc[mt][nt], ah, bv.z, bv.w);
                    mma_bf16(acc[mt][nt], al, bv.x, bv.y);
                }
            }
        }
    }

    const float scale = 0.08838834764831845f;  // 1/sqrt(128)
    float* S = g_scores + ((size_t)b * SQ + (size_t)qb * 128) * SK + (size_t)kb * 128;
#pragma unroll
    for (int mt = 0; mt < 2; mt++)
#pragma unroll
        for (int nt = 0; nt < 8; nt++) {
            int qr = qoff + mt * 16 + g;
            int kc = koff + nt * 8 + 2 * tg;
            *(float2*)(S + (size_t)qr * SK + kc) =
                make_float2(acc[mt][nt][0] * scale, acc[mt][nt][1] * scale);
            *(float2*)(S + (size_t)(qr + 8) * SK + kc) =
                make_float2(acc[mt][nt][2] * scale, acc[mt][nt][3] * scale);
        }
}

// ---------------------------------------------------------------------------
// Kernel B: row softmax with mask. One CTA per (b,q) row. Max over all k
// pre-mask (shift-invariant, matches reference). Writes P once to dst
// (attn output when available, else in-place in g_scores).
// ---------------------------------------------------------------------------
__global__ __launch_bounds__(256)
void softmax_kernel(const int* __restrict__ mask, float* __restrict__ pdst)
{
    const int q = blockIdx.x;
    const int b = blockIdx.y;
    const size_t base = ((size_t)b * SQ + q) * SK;
    const float* row = g_scores + base;
    float* dst = (pdst != nullptr ? pdst : g_scores) + base;
    const int* mrow = mask + base;
    const int tid = threadIdx.x;

    float4 f0 = ((const float4*)row)[tid];
    float4 f1 = ((const float4*)row)[tid + 256];
    int4   m0 = ((const int4*)mrow)[tid];
    int4   m1 = ((const int4*)mrow)[tid + 256];

    float v[8] = {f0.x, f0.y, f0.z, f0.w, f1.x, f1.y, f1.z, f1.w};
    int   m[8] = {m0.x, m0.y, m0.z, m0.w, m1.x, m1.y, m1.z, m1.w};

    float mx = v[0];
#pragma unroll
    for (int i = 1; i < 8; i++) mx = fmaxf(mx, v[i]);

    __shared__ float red[8];
#pragma unroll
    for (int off = 16; off > 0; off >>= 1)
        mx = fmaxf(mx, __shfl_xor_sync(0xffffffffu, mx, off));
    if ((tid & 31) == 0) red[tid >> 5] = mx;
    __syncthreads();
    if (tid < 32) {
        float t = (tid < 8) ? red[tid] : -3.402823466e38f;
#pragma unroll
        for (int off = 4; off > 0; off >>= 1)
            t = fmaxf(t, __shfl_xor_sync(0xffffffffu, t, off));
        if (tid == 0) red[0] = t;
    }
    __syncthreads();
    mx = red[0];

    float e[8];
    float s = 0.f;
#pragma unroll
    for (int i = 0; i < 8; i++) {
        e[i] = (m[i] != 0) ? __expf(v[i] - mx) : 0.f;
        s += e[i];
    }
#pragma unroll
    for (int off = 16; off > 0; off >>= 1)
        s += __shfl_xor_sync(0xffffffffu, s, off);
    __shared__ float red2[8];
    if ((tid & 31) == 0) red2[tid >> 5] = s;
    __syncthreads();
    if (tid < 32) {
        float t = (tid < 8) ? red2[tid] : 0.f;
#pragma unroll
        for (int off = 4; off > 0; off >>= 1)
            t += __shfl_xor_sync(0xffffffffu, t, off);
        if (tid == 0) red2[0] = t;
    }
    __syncthreads();
    const float inv = 1.0f / red2[0];

    ((float4*)dst)[tid]       = make_float4(e[0] * inv, e[1] * inv, e[2] * inv, e[3] * inv);
    ((float4*)dst)[tid + 256] = make_float4(e[4] * inv, e[5] * inv, e[6] * inv, e[7] * inv);
}

// ---------------------------------------------------------------------------
// Kernel C: context = P @ V. CTA 64q x 128v, 8 warps (2x4), warp 32x32.
// V via cp.async (pre-packed); P split in-flight with distance-2 register
// prefetch. Slot rotation: group i of row r stored at position (i+r)&3 ->
// consumer reads position (tg+R)&3 to get group tg. Rows R and R+8 share
// rotation since 8 = 0 mod 4. Dynamic smem: 72 KB.
// ---------------------------------------------------------------------------
__device__ __forceinline__ void sts_p_chunk(uint32_t base, const float4* pf, int r, int c)
{
    float f[16] = {pf[0].x, pf[0].y, pf[0].z, pf[0].w,
                   pf[1].x, pf[1].y, pf[1].z, pf[1].w,
                   pf[2].x, pf[2].y, pf[2].z, pf[2].w,
                   pf[3].x, pf[3].y, pf[3].z, pf[3].w};
    unsigned hw[8], lw[8];
#pragma unroll
    for (int i = 0; i < 8; i++) {
        __nv_bfloat16 ha, la, hb, lb;
        split1(f[2 * i], ha, la);
        split1(f[2 * i + 1], hb, lb);
        hw[i] = pack_bf16(ha, hb);
        lw[i] = pack_bf16(la, lb);
    }
#pragma unroll
    for (int i = 0; i < 4; i++) {
        int slot = (i + r) & 3;   // group i -> position (i+r)&3
        sts128(base + r * RSTRIDE + c * 64 + slot * 16,
               make_uint4(hw[i], hw[4 + i], lw[i], lw[4 + i]));
    }
}

__global__ __launch_bounds__(256, 2)
void pv_mma_kernel(const float* __restrict__ Pext, float* __restrict__ ctx)
{
    extern __shared__ char smem[];
    const int qb = blockIdx.x, b = blockIdx.y;
    const int tid = threadIdx.x, wid = tid >> 5, lane = tid & 31;
    const int g = lane >> 2, tg = lane & 3;
    const int qoff = (wid >> 2) * 32, noff = (wid & 3) * 32;

    const float* P = (Pext != nullptr) ? Pext : g_scores;
    const float* Pb = P + ((size_t)b * SQ + (size_t)qb * 64) * SK;
    const uint4* vpk = g_vpk + (size_t)b * DV * (SK / 16) * 4;

    const uint32_t sb = (uint32_t)__cvta_generic_to_shared(smem);
    const uint32_t sP[2] = { sb,          sb + 12288 };
    const uint32_t sV[2] = { sb + 24576,  sb + 49152 };

    const int pr = tid >> 1, pc = tid & 1;   // P staging coords (tid < 128)

    float4 pf[2][4];

    // prolog: P chunks 0,1 into regs; chunk 0 into smem; V chunk 0 async
    if (tid < 128) {
        const float4* prow = (const float4*)(Pb + (size_t)pr * SK);
#pragma unroll
        for (int i = 0; i < 4; i++) pf[0][i] = prow[pc * 4 + i];
#pragma unroll
        for (int i = 0; i < 4; i++) pf[1][i] = prow[8 + pc * 4 + i];
        sts_p_chunk(sP[0], pf[0], pr, pc);
    }
    {
#pragma unroll
        for (int i = 0; i < 4; i++) {
            int u = i * 256 + tid;
            int row = u >> 3, c = (u >> 2) & 1, t = u & 3;
            CP_ASYNC16(sV[0] + row * RSTRIDE + c * 64 + t * 16,
                       vpk + ((size_t)row * (SK / 16) + c) * 4 + t);
        }
        CP_COMMIT();
    }

    float acc[2][4][4];
#pragma unroll
    for (int i = 0; i < 2; i++)
#pragma unroll
        for (int j = 0; j < 4; j++)
#pragma unroll
            for (int v = 0; v < 4; v++) acc[i][j][v] = 0.f;

    const int NIT = SK / 32;  // 64
    for (int it = 0; it < NIT; it++) {
        CP_WAIT0();
        __syncthreads();
        if (it + 1 < NIT) {
            const int cg = (it + 1) * 2;
#pragma unroll
            for (int i = 0; i < 4; i++) {
                int u = i * 256 + tid;
                int row = u >> 3, c = (u >> 2) & 1, t = u & 3;
                CP_ASYNC16(sV[(it + 1) & 1] + row * RSTRIDE + c * 64 + t * 16,
                           vpk + ((size_t)row * (SK / 16) + cg + c) * 4 + t);
            }
            CP_COMMIT();
        }
        if (it + 2 < NIT && tid < 128) {
            const float4* pn = (const float4*)(Pb + (size_t)pr * SK) + (it + 2) * 8 + pc * 4;
#pragma unroll
            for (int i = 0; i < 4; i++) pf[it & 1][i] = pn[i];
        }

        const uint32_t pbuf = sP[it & 1], vbuf = sV[it & 1];
#pragma unroll
        for (int c = 0; c < 2; c++) {
            uint4 av[2][2];
#pragma unroll
            for (int mt = 0; mt < 2; mt++) {
                int R = qoff + mt * 16 + g;
                int slot = (tg + R) & 3;   // position holding group tg of rows R, R+8
                av[mt][0] = lds128(pbuf + R * RSTRIDE + c * 64 + slot * 16);
                av[mt][1] = lds128(pbuf + (R + 8) * RSTRIDE + c * 64 + slot * 16);
            }
#pragma unroll
            for (int nt = 0; nt < 4; nt++) {
                uint4 bv = lds128(vbuf + (noff + nt * 8 + g) * RSTRIDE + c * 64 + tg * 16);
#pragma unroll
                for (int mt = 0; mt < 2; mt++) {
                    unsigned ah[4] = {av[mt][0].x, av[mt][1].x, av[mt][0].y, av[mt][1].y};
                    unsigned al[4] = {av[mt][0].z, av[mt][1].z, av[mt][0].w, av[mt][1].w};
                    mma_bf16(acc[mt][nt], ah, bv.x, bv.y);
                    mma_bf16(acc[mt][nt], ah, bv.z, bv.w);
                    mma_bf16(acc[mt][nt], al, bv.x, bv.y);
                }
            }
        }
        if (it + 1 < NIT && tid < 128)
            sts_p_chunk(sP[(it + 1) & 1], pf[(it + 1) & 1], pr, pc);
    }

    float* Cb = ctx + ((size_t)b * SQ + (size_t)qb * 64) * DV;
#pragma unroll
    for (int mt = 0; mt < 2; mt++)
#pragma unroll
        for (int nt = 0; nt < 4; nt++) {
            int qr = qoff + mt * 16 + g;
            int vc = noff + nt * 8 + 2 * tg;
            *(float2*)(Cb + (size_t)qr * DV + vc) =
                make_float2(acc[mt][nt][0], acc[mt][nt][1]);
            *(float2*)(Cb + (size_t)(qr + 8) * DV + vc) =
                make_float2(acc[mt][nt][2], acc[mt][nt][3]);
        }
}

// ---------------------------------------------------------------------------
// Launch
// ---------------------------------------------------------------------------
extern "C" void kernel_launch(void* const* d_in, const int* in_sizes, int n_in,
                              void* d_out, int out_size)
{
    const float* Q    = (const float*)d_in[0];
    const float* K    = (const float*)d_in[1];
    const float* V    = (const float*)d_in[2];
    const int*   mask = (const int*)d_in[3];
    float* out = (float*)d_out;

    const size_t CTX  = (size_t)BATCH * SQ * DV;   //  4,194,304
    const size_t ATTN = (size_t)BATCH * SQ * SK;   // 67,108,864

    float* ctx_out  = nullptr;
    float* attn_out = nullptr;
    const size_t osz = (size_t)out_size;
    if (osz == CTX + ATTN)      { ctx_out = out; attn_out = out + CTX; }
    else if (osz == ATTN)       { attn_out = out; }
    else if (osz == CTX)        { ctx_out = out; }
    else                        { ctx_out = out; if (osz >= CTX + ATTN) attn_out = out + CTX; }

    // Idempotent, executes immediately (legal under capture), no static guards.
    cudaFuncSetAttribute(qk_mma_kernel, cudaFuncAttributeMaxDynamicSharedMemorySize, 98304);
    cudaFuncSetAttribute(pv_mma_kernel, cudaFuncAttributeMaxDynamicSharedMemorySize, 73728);

    // Prep: pack Q, K, V
    qkprep_kernel<<<1024, 256>>>((const float4*)Q, 0);
    qkprep_kernel<<<1024, 256>>>((const float4*)K, 1);
    {
        dim3 grid(SK / 32, DV / 64, BATCH);
        vprep_kernel<<<grid, dim3(64, 4)>>>(V);
    }

    // A: scores
    {
        dim3 grid(SK / 128, SQ / 128, BATCH);
        qk_mma_kernel<<<grid, 256, 98304>>>();
    }

    // B: softmax -> P (to attn output when present, else in-place scratch)
    {
        dim3 grid(SQ, BATCH);
        softmax_kernel<<<grid, 256>>>(mask, attn_out);
    }

    // C: context
    if (ctx_out != nullptr) {
        dim3 grid(SQ / 64, BATCH);
        pv_mma_kernel<<<grid, 256, 73728>>>(attn_out, ctx_out);
    }
}